// round 6
// baseline (speedup 1.0000x reference)
#include <cuda_runtime.h>
#include <cstdint>

#define EPSF 1e-20f

static const int Bn = 8, Cn = 32, Hn = 256, Wn = 256;
static const int OWn = 511;
#define IMG_IN  65536      // 256*256
#define IMG_OUT 261121     // 511*511
#define TOT_OUT 66846976   // 8*32*511*511

// Packed per-channel constants:
// [0..8]  = softplus(w) (row-major 3x3)
// [9..12] = 1/(parity-sum + EPS) for ee, eo, oe, oo
// [13]    = bias
__device__ __align__(16) float g_pack[Cn][16];

__global__ void prep_kernel(const float* __restrict__ sw,
                            const float* __restrict__ bias) {
    int c = threadIdx.x;
    if (c >= Cn) return;
    float w[9];
#pragma unroll
    for (int i = 0; i < 9; i++) {
        float x = sw[c * 9 + i];
        float s = (x > 20.0f) ? x : log1pf(expf(x));
        w[i] = s;
        g_pack[c][i] = s;
    }
    g_pack[c][9]  = 1.0f / (w[4] + EPSF);                         // ee: w11
    g_pack[c][10] = 1.0f / (w[3] + w[5] + EPSF);                  // eo: w10+w12
    g_pack[c][11] = 1.0f / (w[1] + w[7] + EPSF);                  // oe: w01+w21
    g_pack[c][12] = 1.0f / (w[0] + w[2] + w[6] + w[8] + EPSF);    // oo
    g_pack[c][13] = bias[c];
    g_pack[c][14] = 0.0f;
    g_pack[c][15] = 0.0f;
}

__device__ __forceinline__ float frcp(float x) {
    float r;
    asm("rcp.approx.f32 %0, %1;" : "=f"(r) : "f"(x));
    return r;
}

// Store 4 (or 3) consecutive floats with best available vector width.
// Alignment of p is warp-uniform (ox steps are multiples of 16B), so the
// branches do not diverge.
__device__ __forceinline__ void store_group(float* p, float v0, float v1,
                                            float v2, float v3, bool has3) {
    unsigned a = (unsigned)((uintptr_t)p & 15);
    if (has3) {
        if (a == 0) {
            *reinterpret_cast<float4*>(p) = make_float4(v0, v1, v2, v3);
        } else if (a == 8) {
            *reinterpret_cast<float2*>(p)     = make_float2(v0, v1);
            *reinterpret_cast<float2*>(p + 2) = make_float2(v2, v3);
        } else {  // a == 4 or 12: p+1 is 8B aligned
            p[0] = v0;
            *reinterpret_cast<float2*>(p + 1) = make_float2(v1, v2);
            p[3] = v3;
        }
    } else {  // only 3 valid values (last column group)
        if ((a & 7) == 0) {
            *reinterpret_cast<float2*>(p) = make_float2(v0, v1);
            p[2] = v2;
        } else {
            p[0] = v0;
            *reinterpret_cast<float2*>(p + 1) = make_float2(v1, v2);
        }
    }
}

// One thread: input footprint rows {r, r+1} x cols {c0, c0+1, c0+2},
// produces output rows {2r, 2r+1} x cols {4t .. 4t+3}.
// Tap map (oy = 2*iy + ky - 1, ox = 2*ix + kx - 1):
//   even oy -> ky=1, iy=r ; odd oy -> ky=0 iy=r+1, ky=2 iy=r  (same in x)
__global__ __launch_bounds__(256) void deconv_kernel(
    const float* __restrict__ din,
    const float* __restrict__ cin,
    float* __restrict__ out) {
    const int t = blockIdx.x * 32 + threadIdx.x;  // 0..127  (column pair)
    const int r = blockIdx.y * 8 + threadIdx.y;   // 0..255
    const int z = blockIdx.z;                     // b*C + ch
    const int ch = z & (Cn - 1);

    const float4* qp = reinterpret_cast<const float4*>(&g_pack[ch][0]);
    const float4 q0 = qp[0], q1 = qp[1], q2 = qp[2], q3 = qp[3];
    const float w00 = q0.x, w01 = q0.y, w02 = q0.z, w10 = q0.w;
    const float w11 = q1.x, w12 = q1.y, w20 = q1.z, w21 = q1.w;
    const float w22 = q2.x;
    const float i_ee = q2.y, i_eo = q2.z, i_oe = q2.w, i_oo = q3.x;
    const float bias = q3.y;

    const float* dp = din + (long)z * IMG_IN;
    const float* cp = cin + (long)z * IMG_IN;

    const int c0 = t * 2;
    const bool has3 = (t < 127);   // ox=4t+3 <= 510  <=> col c0+2 exists
    const bool hasR = (r < 255);   // oy=2r+1 <= 509  <=> row r+1 exists

    const int rowA = r * Wn + c0;
    const float2 dav = *reinterpret_cast<const float2*>(dp + rowA);
    const float2 cav = *reinterpret_cast<const float2*>(cp + rowA);
    const float da2 = has3 ? __ldg(dp + rowA + 2) : 0.0f;
    const float ca2 = has3 ? __ldg(cp + rowA + 2) : 0.0f;
    float2 dev = make_float2(0.f, 0.f), cev = make_float2(0.f, 0.f);
    float de2 = 0.f, ce2 = 0.f;
    if (hasR) {
        const int rowB = rowA + Wn;
        dev = *reinterpret_cast<const float2*>(dp + rowB);
        cev = *reinterpret_cast<const float2*>(cp + rowB);
        if (has3) {
            de2 = __ldg(dp + rowB + 2);
            ce2 = __ldg(cp + rowB + 2);
        }
    }

    // products cd*d
    const float pa0 = cav.x * dav.x, pa1 = cav.y * dav.y, pa2 = ca2 * da2;
    const float pe0 = cev.x * dev.x, pe1 = cev.y * dev.y, pe2 = ce2 * de2;

    float* outD = out;
    float* outC = out + TOT_OUT;
    const long obase = (long)z * IMG_OUT + (long)(2 * r) * OWn + 4 * t;

    // ---- even output row (oy = 2r): ee / eo taps ----
    {
        const float den0 = cav.x * w11;                      // ee @ c0
        const float den1 = cav.y * w10 + cav.x * w12;        // eo @ c0
        const float den2 = cav.y * w11;                      // ee @ c0+1
        const float den3 = ca2  * w10 + cav.y * w12;         // eo @ c0+1
        const float nom0 = pa0 * w11;
        const float nom1 = pa1 * w10 + pa0 * w12;
        const float nom2 = pa1 * w11;
        const float nom3 = pa2 * w10 + pa1 * w12;

        store_group(outD + obase,
                    nom0 * frcp(den0 + EPSF) + bias,
                    nom1 * frcp(den1 + EPSF) + bias,
                    nom2 * frcp(den2 + EPSF) + bias,
                    nom3 * frcp(den3 + EPSF) + bias, has3);
        store_group(outC + obase,
                    den0 * i_ee, den1 * i_eo, den2 * i_ee, den3 * i_eo, has3);
    }

    // ---- odd output row (oy = 2r+1): oe / oo taps ----
    if (hasR) {
        const float den0 = cev.x * w01 + cav.x * w21;                          // oe @ c0
        const float den1 = cev.y * w00 + cev.x * w02 + cav.y * w20 + cav.x * w22;  // oo @ c0
        const float den2 = cev.y * w01 + cav.y * w21;                          // oe @ c0+1
        const float den3 = ce2  * w00 + cev.y * w02 + ca2  * w20 + cav.y * w22;    // oo @ c0+1
        const float nom0 = pe0 * w01 + pa0 * w21;
        const float nom1 = pe1 * w00 + pe0 * w02 + pa1 * w20 + pa0 * w22;
        const float nom2 = pe1 * w01 + pa1 * w21;
        const float nom3 = pe2 * w00 + pe1 * w02 + pa2 * w20 + pa1 * w22;

        const long ob2 = obase + OWn;
        store_group(outD + ob2,
                    nom0 * frcp(den0 + EPSF) + bias,
                    nom1 * frcp(den1 + EPSF) + bias,
                    nom2 * frcp(den2 + EPSF) + bias,
                    nom3 * frcp(den3 + EPSF) + bias, has3);
        store_group(outC + ob2,
                    den0 * i_oe, den1 * i_oo, den2 * i_oe, den3 * i_oo, has3);
    }
}

extern "C" void kernel_launch(void* const* d_in, const int* in_sizes, int n_in,
                              void* d_out, int out_size) {
    const float* d    = (const float*)d_in[0];
    const float* cd   = (const float*)d_in[1];
    const float* sw   = (const float*)d_in[2];
    const float* bias = (const float*)d_in[3];
    float* out = (float*)d_out;

    prep_kernel<<<1, 32>>>(sw, bias);

    dim3 blk(32, 8, 1);
    dim3 grd(4, 32, Bn * Cn);   // 128 col-pairs / 32, 256 rows / 8, 256 images
    deconv_kernel<<<grd, blk>>>(d, cd, out);
}

// round 7
// speedup vs baseline: 1.0074x; 1.0074x over previous
#include <cuda_runtime.h>
#include <cstdint>

#define EPSF 1e-20f

static const int Bn = 8, Cn = 32, Hn = 256, Wn = 256;
static const int OWn = 511;
#define IMG_IN  65536      // 256*256
#define IMG_OUT 261121     // 511*511
#define TOT_OUT 66846976   // 8*32*511*511

// Packed per-channel constants:
// [0..8]  = softplus(w) (row-major 3x3)
// [9..12] = 1/(parity-sum + EPS) for ee, eo, oe, oo
// [13]    = bias
__device__ __align__(16) float g_pack[Cn][16];

__global__ void prep_kernel(const float* __restrict__ sw,
                            const float* __restrict__ bias) {
    int c = threadIdx.x;
    if (c >= Cn) return;
    float w[9];
#pragma unroll
    for (int i = 0; i < 9; i++) {
        float x = sw[c * 9 + i];
        float s = (x > 20.0f) ? x : log1pf(expf(x));
        w[i] = s;
        g_pack[c][i] = s;
    }
    g_pack[c][9]  = 1.0f / (w[4] + EPSF);                         // ee: w11
    g_pack[c][10] = 1.0f / (w[3] + w[5] + EPSF);                  // eo: w10+w12
    g_pack[c][11] = 1.0f / (w[1] + w[7] + EPSF);                  // oe: w01+w21
    g_pack[c][12] = 1.0f / (w[0] + w[2] + w[6] + w[8] + EPSF);    // oo
    g_pack[c][13] = bias[c];
    g_pack[c][14] = 0.0f;
    g_pack[c][15] = 0.0f;
}

__device__ __forceinline__ float frcp(float x) {
    float r;
    asm("rcp.approx.f32 %0, %1;" : "=f"(r) : "f"(x));
    return r;
}

// Candidate evaluators on the local 4-col input window.
// Even output row (oy=2r, input row r only):
#define EV_D(k)  (cA[k] * w11)
#define EV_N(k)  (pA[k] * w11)
#define OD_D(k)  (fmaf(cA[(k)+1], w10, cA[k] * w12))
#define OD_N(k)  (fmaf(pA[(k)+1], w10, pA[k] * w12))
// Odd output row (oy=2r+1, input rows r ("A", ky=2) and r+1 ("E", ky=0)):
#define OE_D(k)  (fmaf(cE[k], w01, cA[k] * w21))
#define OE_N(k)  (fmaf(pE[k], w01, pA[k] * w21))
#define OO_D(k)  (fmaf(cE[(k)+1], w00, fmaf(cE[k], w02, fmaf(cA[(k)+1], w20, cA[k] * w22))))
#define OO_N(k)  (fmaf(pE[(k)+1], w00, fmaf(pE[k], w02, fmaf(pA[(k)+1], w20, pA[k] * w22))))

// Full thread t (0..126): input cols [2t, 2t+3], writes 4 ALIGNED output cols
// per row: row0 at ox = s0+4t.. , row1 at ox = s1+4t..  (s1 = (s0+1)&3).
// Boundary lane (tglob==127): the 3 leftover edge columns per row, scalar.
__global__ __launch_bounds__(256, 5) void deconv_kernel(
    const float* __restrict__ din,
    const float* __restrict__ cin,
    float* __restrict__ out) {
    const int tg = blockIdx.x * 32 + threadIdx.x;  // 0..127
    const int r  = blockIdx.y * 8 + threadIdx.y;   // 0..255
    const int z  = blockIdx.z;                     // b*C + ch
    const int ch = z & (Cn - 1);

    const float4* qp = reinterpret_cast<const float4*>(&g_pack[ch][0]);
    const float4 q0 = qp[0], q1 = qp[1], q2 = qp[2], q3 = qp[3];
    const float w00 = q0.x, w01 = q0.y, w02 = q0.z, w10 = q0.w;
    const float w11 = q1.x, w12 = q1.y, w20 = q1.z, w21 = q1.w;
    const float w22 = q2.x;
    const float i_ee = q2.y, i_eo = q2.z, i_oe = q2.w, i_oo = q3.x;
    const float bias = q3.y;

    const float* dp = din + (long)z * IMG_IN;
    const float* cp = cin + (long)z * IMG_IN;
    float* outD = out;
    float* outC = out + TOT_OUT;

    const int  s0   = (4 - ((z + 2 * r) & 3)) & 3;   // row0 misalign shift
    const int  s1   = (s0 + 1) & 3;                  // row1 shift
    const bool hasR = (r < 255);
    const long base0 = (long)z * IMG_OUT + (long)(2 * r) * OWn;

    if (tg < 127) {
        const int cb   = 2 * tg;
        const int rowA = r * Wn + cb;
        const float2 dA01 = *reinterpret_cast<const float2*>(dp + rowA);
        const float2 dA23 = *reinterpret_cast<const float2*>(dp + rowA + 2);
        const float2 cA01 = *reinterpret_cast<const float2*>(cp + rowA);
        const float2 cA23 = *reinterpret_cast<const float2*>(cp + rowA + 2);
        const float cA[4] = {cA01.x, cA01.y, cA23.x, cA23.y};
        const float pA[4] = {cA01.x * dA01.x, cA01.y * dA01.y,
                             cA23.x * dA23.x, cA23.y * dA23.y};
        float cE[4] = {0.f, 0.f, 0.f, 0.f};
        float pE[4] = {0.f, 0.f, 0.f, 0.f};
        if (hasR) {
            const int rowB = rowA + Wn;
            const float2 dE01 = *reinterpret_cast<const float2*>(dp + rowB);
            const float2 dE23 = *reinterpret_cast<const float2*>(dp + rowB + 2);
            const float2 cE01 = *reinterpret_cast<const float2*>(cp + rowB);
            const float2 cE23 = *reinterpret_cast<const float2*>(cp + rowB + 2);
            cE[0] = cE01.x; cE[1] = cE01.y; cE[2] = cE23.x; cE[3] = cE23.y;
            pE[0] = cE01.x * dE01.x; pE[1] = cE01.y * dE01.y;
            pE[2] = cE23.x * dE23.x; pE[3] = cE23.y * dE23.y;
        }

        float ed0, ed1, ed2, ed3, en0, en1, en2, en3;  // even output row
        float od0, od1, od2, od3, on0, on1, on2, on3;  // odd output row
        switch (s0) {  // warp-uniform
        case 0:  // row0: e0 o0 e1 o1   row1(s1=1): o0 e1 o1 e2
            ed0 = EV_D(0); ed1 = OD_D(0); ed2 = EV_D(1); ed3 = OD_D(1);
            en0 = EV_N(0); en1 = OD_N(0); en2 = EV_N(1); en3 = OD_N(1);
            od0 = OO_D(0); od1 = OE_D(1); od2 = OO_D(1); od3 = OE_D(2);
            on0 = OO_N(0); on1 = OE_N(1); on2 = OO_N(1); on3 = OE_N(2);
            break;
        case 1:  // row0: o0 e1 o1 e2   row1(s1=2): e1 o1 e2 o2
            ed0 = OD_D(0); ed1 = EV_D(1); ed2 = OD_D(1); ed3 = EV_D(2);
            en0 = OD_N(0); en1 = EV_N(1); en2 = OD_N(1); en3 = EV_N(2);
            od0 = OE_D(1); od1 = OO_D(1); od2 = OE_D(2); od3 = OO_D(2);
            on0 = OE_N(1); on1 = OO_N(1); on2 = OE_N(2); on3 = OO_N(2);
            break;
        case 2:  // row0: e1 o1 e2 o2   row1(s1=3): o1 e2 o2 e3
            ed0 = EV_D(1); ed1 = OD_D(1); ed2 = EV_D(2); ed3 = OD_D(2);
            en0 = EV_N(1); en1 = OD_N(1); en2 = EV_N(2); en3 = OD_N(2);
            od0 = OO_D(1); od1 = OE_D(2); od2 = OO_D(2); od3 = OE_D(3);
            on0 = OO_N(1); on1 = OE_N(2); on2 = OO_N(2); on3 = OE_N(3);
            break;
        default:  // s0=3  row0: o1 e2 o2 e3   row1(s1=0): e0 o0 e1 o1
            ed0 = OD_D(1); ed1 = EV_D(2); ed2 = OD_D(2); ed3 = EV_D(3);
            en0 = OD_N(1); en1 = EV_N(2); en2 = OD_N(2); en3 = EV_N(3);
            od0 = OE_D(0); od1 = OO_D(0); od2 = OE_D(1); od3 = OO_D(1);
            on0 = OE_N(0); on1 = OO_N(0); on2 = OE_N(1); on3 = OO_N(1);
            break;
        }

        // parity-sum reciprocals alternate with column parity
        const float rE0 = (s0 & 1) ? i_eo : i_ee;
        const float rE1 = (s0 & 1) ? i_ee : i_eo;
        const float rO0 = (s1 & 1) ? i_oo : i_oe;
        const float rO1 = (s1 & 1) ? i_oe : i_oo;

        const long off0 = base0 + s0 + 4 * tg;  // 16B aligned
        float4 vD, vC;
        vD.x = en0 * frcp(ed0 + EPSF) + bias;
        vD.y = en1 * frcp(ed1 + EPSF) + bias;
        vD.z = en2 * frcp(ed2 + EPSF) + bias;
        vD.w = en3 * frcp(ed3 + EPSF) + bias;
        vC.x = ed0 * rE0; vC.y = ed1 * rE1; vC.z = ed2 * rE0; vC.w = ed3 * rE1;
        *reinterpret_cast<float4*>(outD + off0) = vD;
        *reinterpret_cast<float4*>(outC + off0) = vC;

        if (hasR) {
            const long off1 = base0 + OWn + s1 + 4 * tg;  // 16B aligned
            vD.x = on0 * frcp(od0 + EPSF) + bias;
            vD.y = on1 * frcp(od1 + EPSF) + bias;
            vD.z = on2 * frcp(od2 + EPSF) + bias;
            vD.w = on3 * frcp(od3 + EPSF) + bias;
            vC.x = od0 * rO0; vC.y = od1 * rO1; vC.z = od2 * rO0; vC.w = od3 * rO1;
            *reinterpret_cast<float4*>(outD + off1) = vD;
            *reinterpret_cast<float4*>(outC + off1) = vC;
        }
    } else {
        // boundary lane: 3 leftover columns per output row (head [0,s) + tail)
        const float* dR = dp + r * Wn;
        const float* cR = cp + r * Wn;
        const float* dS = dR + Wn;  // valid only if hasR
        const float* cS = cR + Wn;
#pragma unroll
        for (int i = 0; i < 3; i++) {
            // even output row (oy = 2r)
            {
                const int ox = (i < s0) ? i : 508 + i;
                float den, nom, rc;
                if ((ox & 1) == 0) {
                    const int j = ox >> 1;
                    const float c = cR[j];
                    den = c * w11;
                    nom = c * dR[j] * w11;
                    rc  = i_ee;
                } else {
                    const int j = ox >> 1;
                    const float c1 = cR[j + 1], c0 = cR[j];
                    den = c1 * w10 + c0 * w12;
                    nom = c1 * dR[j + 1] * w10 + c0 * dR[j] * w12;
                    rc  = i_eo;
                }
                const long o = base0 + ox;
                outD[o] = nom * frcp(den + EPSF) + bias;
                outC[o] = den * rc;
            }
            // odd output row (oy = 2r+1)
            if (hasR) {
                const int ox = (i < s1) ? i : 508 + i;
                float den, nom, rc;
                if ((ox & 1) == 0) {
                    const int j = ox >> 1;
                    const float ce = cS[j], ca = cR[j];
                    den = ce * w01 + ca * w21;
                    nom = ce * dS[j] * w01 + ca * dR[j] * w21;
                    rc  = i_oe;
                } else {
                    const int j = ox >> 1;
                    const float ce1 = cS[j + 1], ce0 = cS[j];
                    const float ca1 = cR[j + 1], ca0 = cR[j];
                    den = ce1 * w00 + ce0 * w02 + ca1 * w20 + ca0 * w22;
                    nom = ce1 * dS[j + 1] * w00 + ce0 * dS[j] * w02 +
                          ca1 * dR[j + 1] * w20 + ca0 * dR[j] * w22;
                    rc  = i_oo;
                }
                const long o = base0 + OWn + ox;
                outD[o] = nom * frcp(den + EPSF) + bias;
                outC[o] = den * rc;
            }
        }
    }
}

extern "C" void kernel_launch(void* const* d_in, const int* in_sizes, int n_in,
                              void* d_out, int out_size) {
    const float* d    = (const float*)d_in[0];
    const float* cd   = (const float*)d_in[1];
    const float* sw   = (const float*)d_in[2];
    const float* bias = (const float*)d_in[3];
    float* out = (float*)d_out;

    prep_kernel<<<1, 32>>>(sw, bias);

    dim3 blk(32, 8, 1);
    dim3 grd(4, 32, Bn * Cn);   // 128 col-group threads, 256 rows / 8, 256 images
    deconv_kernel<<<grd, blk>>>(d, cd, out);
}